// round 12
// baseline (speedup 1.0000x reference)
#include <cuda_runtime.h>
#include <math.h>
#include <stdint.h>

#define N_TOK 16384
#define DIM   2048
#define NEXP  64
#define KSEL  9
#define EPS_C 0.01f
#define INV_SIG_SQRT2 45.254833995939045f

#define BM 112
#define GRID 147                   // ceil(16384/112)
#define BK 32
#define NCHUNK (DIM / BK)          // 64
#define NSTAGE 4
#define XTS 36                     // x smem row stride (u32)
#define XTILE (BM * XTS)           // 4032 u32
#define WTILE (BK * 128)           // 4096 u32
#define STAGEU (XTILE + WTILE)     // 8128 u32 = 32512 B
#define SMEM_BYTES (NSTAGE * STAGEU * 4)   // 130048 B
#define XV4 (BM * 8)               // 896 float4 per x stage
#define LGS 132                    // logits smem row stride (u32)

__device__ __forceinline__ unsigned long long pack_dup(float a) {
    unsigned long long r;
    unsigned ai = __float_as_uint(a);
    asm("mov.b64 %0, {%1, %1};" : "=l"(r) : "r"(ai));
    return r;
}
__device__ __forceinline__ uint32_t smem_u32(const void* p) {
    uint32_t a;
    asm("{ .reg .u64 t; cvta.to.shared.u64 t, %1; cvt.u32.u64 %0, t; }"
        : "=r"(a) : "l"(p));
    return a;
}
__device__ __forceinline__ void cp16(uint32_t dst, const void* src) {
    asm volatile("cp.async.ca.shared.global [%0], [%1], 16;"
                 :: "r"(dst), "l"(src) : "memory");
}
__device__ __forceinline__ uint32_t redux_max(uint32_t v) {
    uint32_t r;
    asm("redux.sync.max.u32 %0, %1, 0xffffffff;" : "=r"(r) : "r"(v));
    return r;
}
__device__ __forceinline__ uint32_t ordkey(float f) {
    uint32_t u = __float_as_uint(f);
    return ((int)u < 0) ? ~u : (u | 0x80000000u);
}
__device__ __forceinline__ float ordinv(uint32_t k) {
    return __uint_as_float(((int)k < 0) ? (k ^ 0x80000000u) : ~k);
}
__device__ __forceinline__ float wsum(float v) {
    #pragma unroll
    for (int o = 16; o; o >>= 1) v += __shfl_xor_sync(0xffffffffu, v, o);
    return v;
}

// ---------------- fused GEMM (round-8 mainloop verbatim) + in-CTA epilogue ----------------
extern "C" __global__ void __launch_bounds__(256, 1)
fused_kernel(const float* __restrict__ x,  const float* __restrict__ Wr,
             const float* __restrict__ Wn, const float* __restrict__ br,
             const float* __restrict__ bn, const float* __restrict__ neps,
             const float* __restrict__ gum, float* __restrict__ out)
{
    extern __shared__ uint32_t smu[];
    const uint32_t sbase = smem_u32(smu);
    const int tid = threadIdx.x;
    const int ty  = tid >> 4;        // 0..15 -> rows 7ty..7ty+6
    const int tx  = tid & 15;        // col pairs 2tx+32j
    const int row0 = blockIdx.x * BM;

    // ---- x cp.async map: 896 float4 over 256 threads x 4 iters (guarded) ----
    const float* xsrc[4];
    uint32_t     xoff[4];
    bool         xact[4];
    #pragma unroll
    for (int i = 0; i < 4; i++) {
        int idx = tid + 256 * i;
        xact[i] = (idx < XV4);
        int r = idx >> 3, seg = idx & 7;
        if (!xact[i]) { r = 0; seg = 0; }
        int grow = row0 + r; if (grow > N_TOK - 1) grow = N_TOK - 1;  // tail clamp
        xsrc[i] = x + (size_t)grow * DIM + seg * 4;
        xoff[i] = (uint32_t)((r * XTS + seg * 4) * 4);
    }
    // ---- W cp.async map ----
    const int wk = tid >> 5, wq = tid & 31;
    const int wcol = wq * 4;
    const float* wsrcbase = (wcol < 64) ? (Wr + wcol) : (Wn + wcol - 64);

    unsigned long long acc[7][4];
    #pragma unroll
    for (int i = 0; i < 7; i++)
        #pragma unroll
        for (int j = 0; j < 4; j++) acc[i][j] = 0ULL;

    auto issue = [&](int c) {
        uint32_t buf = sbase + (uint32_t)((c & (NSTAGE - 1)) * STAGEU * 4);
        #pragma unroll
        for (int i = 0; i < 4; i++)
            if (xact[i]) cp16(buf + xoff[i], xsrc[i] + c * BK);
        #pragma unroll
        for (int i = 0; i < 4; i++) {
            int kk = wk + 8 * i;
            cp16(buf + (uint32_t)((XTILE + kk * 128 + wcol) * 4),
                 wsrcbase + (size_t)(c * BK + kk) * NEXP);
        }
    };

    // prologue: stages 0..2
    #pragma unroll
    for (int p = 0; p < NSTAGE - 1; p++) {
        issue(p);
        asm volatile("cp.async.commit_group;" ::: "memory");
    }

    #pragma unroll 1
    for (int c = 0; c < NCHUNK; c++) {
        if (c < NCHUNK - 2)
            asm volatile("cp.async.wait_group 2;" ::: "memory");
        else if (c == NCHUNK - 2)
            asm volatile("cp.async.wait_group 1;" ::: "memory");
        else
            asm volatile("cp.async.wait_group 0;" ::: "memory");
        __syncthreads();
        if (c + NSTAGE - 1 < NCHUNK) {
            issue(c + NSTAGE - 1);              // stage (c-1)&3: readers passed barrier
            asm volatile("cp.async.commit_group;" ::: "memory");
        }

        const uint32_t* buf = smu + (c & (NSTAGE - 1)) * STAGEU;
        const float* xs = (const float*)buf;
        const float* ws = (const float*)(buf + XTILE);
        #pragma unroll 4
        for (int kk = 0; kk < BK; kk++) {
            unsigned long long b2[4];
            #pragma unroll
            for (int j = 0; j < 4; j++)
                b2[j] = *(const unsigned long long*)(ws + kk * 128 + 2 * tx + 32 * j);
            unsigned long long a2[7];
            #pragma unroll
            for (int i = 0; i < 7; i++)
                a2[i] = pack_dup(xs[(7 * ty + i) * XTS + kk]);
            #pragma unroll
            for (int i = 0; i < 7; i++)
                #pragma unroll
                for (int j = 0; j < 4; j++)
                    asm("fma.rn.f32x2 %0, %1, %2, %0;"
                        : "+l"(acc[i][j]) : "l"(a2[i]), "l"(b2[j]));
        }
    }

    // ---- stage logits into smem (stages 0/1 region; slowest warp reads stage 3) ----
    float* lg_s   = (float*)smu;               // [112][LGS]
    float* imp_s  = lg_s + BM * LGS;            // 64  (inside stage-1 region)
    float* load_s = imp_s + 64;                 // 64
    #pragma unroll
    for (int i = 0; i < 7; i++) {
        int r = 7 * ty + i;
        #pragma unroll
        for (int j = 0; j < 4; j++)
            *(unsigned long long*)(lg_s + r * LGS + 2 * tx + 32 * j) = acc[i][j];
    }
    if (tid < 64) { imp_s[tid] = 0.f; load_s[tid] = 0.f; }
    __syncthreads();

    // ---- per-row epilogue: 8 warps x 14 rows, straight from smem ----
    const int wid = tid >> 5;
    const int lane = tid & 31;
    const int e0 = lane, e1 = lane + 32;
    const float br0 = br[e0], br1 = br[e1];
    const float bn0 = bn[e0], bn1 = bn[e1];
    float impA0 = 0.f, impA1 = 0.f, ldA0 = 0.f, ldA1 = 0.f;

    #pragma unroll 1
    for (int rr = 0; rr < 14; rr++) {
        const int r = wid * 14 + rr;
        const int grow = row0 + r;
        if (grow >= N_TOK) break;               // warp-uniform
        const float* L = lg_s + r * LGS;
        float raw0 = L[e0] + br0,      raw1 = L[e1] + br1;
        float pre0 = L[64 + e0] + bn0, pre1 = L[64 + e1] + bn1;
        float sd0 = fmaxf(pre0, 0.f) + log1pf(expf(-fabsf(pre0))) + EPS_C;
        float sd1 = fmaxf(pre1, 0.f) + log1pf(expf(-fabsf(pre1))) + EPS_C;
        float nz0 = fmaf(neps[(size_t)grow * NEXP + e0], sd0, raw0);
        float nz1 = fmaf(neps[(size_t)grow * NEXP + e1], sd1, raw1);
        float g0 = gum[(size_t)grow * NEXP + e0];
        float g1 = gum[(size_t)grow * NEXP + e1];

        // top-9 via redux.max on orderable keys (exact, tie -> lowest idx)
        uint32_t k0 = ordkey(nz0), k1 = ordkey(nz1);
        float h0 = 0.f, h1 = 0.f, thr = 0.f, m1 = 0.f;
        #pragma unroll 1
        for (int t = 0; t < KSEL; t++) {
            uint32_t M = redux_max(k0 > k1 ? k0 : k1);
            if (t == 0) m1 = ordinv(M);
            thr = ordinv(M);
            unsigned b0 = __ballot_sync(0xffffffffu, k0 == M);
            unsigned b1 = __ballot_sync(0xffffffffu, k1 == M);
            if (b0) {
                if (lane == __ffs(b0) - 1) { h0 = 1.f; k0 = 0u; }
            } else {
                if (lane == __ffs(b1) - 1) { h1 = 1.f; k1 = 0u; }
            }
        }

        float m2 = ordinv(redux_max(ordkey(fmaxf(nz0 + g0, nz1 + g1))));
        float m3 = ordinv(redux_max(ordkey(fmaxf(raw0, raw1))));
        float E10 = expf(nz0 - m1),      E11 = expf(nz1 - m1);
        float E20 = expf(nz0 + g0 - m2), E21 = expf(nz1 + g1 - m2);
        float E30 = expf(raw0 - m3),     E31 = expf(raw1 - m3);
        float i1 = 1.f / wsum(E10 + E11);
        float i2 = 1.f / wsum(E20 + E21);
        float i3 = 1.f / wsum(E30 + E31);

        float ms0 = E20 * i2, ms1 = E21 * i2;
        float* om  = out + (size_t)grow * NEXP;
        float* orp = out + (size_t)N_TOK * NEXP + (size_t)grow * NEXP;
        om[e0]  = (h0 - ms0) + ms0;
        om[e1]  = (h1 - ms1) + ms1;
        orp[e0] = E10 * i1;
        orp[e1] = E11 * i1;

        impA0 += E30 * i3;
        impA1 += E31 * i3;
        float z0 = (thr - raw0) / sd0, z1 = (thr - raw1) / sd1;
        ldA0 += 0.5f * (1.f - erff(z0 * INV_SIG_SQRT2));
        ldA1 += 0.5f * (1.f - erff(z1 * INV_SIG_SQRT2));
    }

    atomicAdd(&imp_s[e0], impA0);
    atomicAdd(&imp_s[e1], impA1);
    atomicAdd(&load_s[e0], ldA0);
    atomicAdd(&load_s[e1], ldA1);
    __syncthreads();
    if (tid < 64) {
        atomicAdd(out + 2 * (size_t)N_TOK * NEXP + tid,        imp_s[tid]);
        atomicAdd(out + 2 * (size_t)N_TOK * NEXP + NEXP + tid, load_s[tid]);
    }
}

extern "C" void kernel_launch(void* const* d_in, const int* in_sizes, int n_in,
                              void* d_out, int out_size)
{
    const float* x    = (const float*)d_in[0];
    const float* Wr   = (const float*)d_in[1];
    const float* br   = (const float*)d_in[2];
    const float* Wn   = (const float*)d_in[3];
    const float* bn   = (const float*)d_in[4];
    const float* neps = (const float*)d_in[5];
    const float* gum  = (const float*)d_in[6];
    float* out = (float*)d_out;

    cudaMemsetAsync(out + 2 * (size_t)N_TOK * NEXP, 0, 2 * NEXP * sizeof(float));

    cudaFuncSetAttribute(fused_kernel,
                         cudaFuncAttributeMaxDynamicSharedMemorySize, SMEM_BYTES);
    fused_kernel<<<GRID, 256, SMEM_BYTES>>>(x, Wr, Wn, br, bn, neps, gum, out);
}

// round 13
// speedup vs baseline: 1.1940x; 1.1940x over previous
#include <cuda_runtime.h>
#include <math.h>
#include <stdint.h>

#define N_TOK 16384
#define DIM   2048
#define NEXP  64
#define KSEL  9
#define EPS_C 0.01f
#define INV_SIG_SQRT2 45.254833995939045f

#define BM 112
#define GRID 147                   // ceil(16384/112)
#define BK 32
#define NCHUNK (DIM / BK)          // 64
#define NSTAGE 4
#define XTS 36                     // x smem row stride (u32)
#define XTILE (BM * XTS)           // 4032 u32
#define WTILE (BK * 128)           // 4096 u32
#define STAGEU (XTILE + WTILE)     // 8128 u32 = 32512 B
#define SMEM_BYTES (NSTAGE * STAGEU * 4)   // 130048 B
#define XV4 (BM * 8)               // 896 float4 per x stage

// logits scratch: [row][128] (0-63 raw dot, 64-127 noise-pre dot) = 8 MB
__device__ __align__(16) float g_lg[(size_t)N_TOK * 128];

__device__ __forceinline__ unsigned long long pack_dup(float a) {
    unsigned long long r;
    unsigned ai = __float_as_uint(a);
    asm("mov.b64 %0, {%1, %1};" : "=l"(r) : "r"(ai));
    return r;
}
__device__ __forceinline__ uint32_t smem_u32(const void* p) {
    uint32_t a;
    asm("{ .reg .u64 t; cvta.to.shared.u64 t, %1; cvt.u32.u64 %0, t; }"
        : "=r"(a) : "l"(p));
    return a;
}
__device__ __forceinline__ void cp16(uint32_t dst, const void* src) {
    asm volatile("cp.async.ca.shared.global [%0], [%1], 16;"
                 :: "r"(dst), "l"(src) : "memory");
}

// ---------------- GEMM: fp32 FFMA2, 112x128 per CTA, 147 CTAs (1/SM) ----------------
// (round-8 proven configuration, verbatim — FROZEN)
extern "C" __global__ void __launch_bounds__(256, 1)
gemm_kernel(const float* __restrict__ x, const float* __restrict__ Wr,
            const float* __restrict__ Wn)
{
    extern __shared__ uint32_t smu[];
    const uint32_t sbase = smem_u32(smu);
    const int tid = threadIdx.x;
    const int ty  = tid >> 4;        // 0..15 -> rows 7ty..7ty+6
    const int tx  = tid & 15;        // col pairs 2tx+32j
    const int row0 = blockIdx.x * BM;

    // ---- x cp.async map: 896 float4 over 256 threads x 4 iters (guarded) ----
    const float* xsrc[4];
    uint32_t     xoff[4];
    bool         xact[4];
    #pragma unroll
    for (int i = 0; i < 4; i++) {
        int idx = tid + 256 * i;
        xact[i] = (idx < XV4);
        int r = idx >> 3, seg = idx & 7;
        if (!xact[i]) { r = 0; seg = 0; }
        int grow = row0 + r; if (grow > N_TOK - 1) grow = N_TOK - 1;  // tail clamp
        xsrc[i] = x + (size_t)grow * DIM + seg * 4;
        xoff[i] = (uint32_t)((r * XTS + seg * 4) * 4);
    }
    // ---- W cp.async map ----
    const int wk = tid >> 5, wq = tid & 31;
    const int wcol = wq * 4;
    const float* wsrcbase = (wcol < 64) ? (Wr + wcol) : (Wn + wcol - 64);

    unsigned long long acc[7][4];
    #pragma unroll
    for (int i = 0; i < 7; i++)
        #pragma unroll
        for (int j = 0; j < 4; j++) acc[i][j] = 0ULL;

    auto issue = [&](int c) {
        uint32_t buf = sbase + (uint32_t)((c & (NSTAGE - 1)) * STAGEU * 4);
        #pragma unroll
        for (int i = 0; i < 4; i++)
            if (xact[i]) cp16(buf + xoff[i], xsrc[i] + c * BK);
        #pragma unroll
        for (int i = 0; i < 4; i++) {
            int kk = wk + 8 * i;
            cp16(buf + (uint32_t)((XTILE + kk * 128 + wcol) * 4),
                 wsrcbase + (size_t)(c * BK + kk) * NEXP);
        }
    };

    // prologue: stages 0..2
    #pragma unroll
    for (int p = 0; p < NSTAGE - 1; p++) {
        issue(p);
        asm volatile("cp.async.commit_group;" ::: "memory");
    }

    #pragma unroll 1
    for (int c = 0; c < NCHUNK; c++) {
        // peeled waits: per-thread pending groups shrink at the tail
        if (c < NCHUNK - 2)
            asm volatile("cp.async.wait_group 2;" ::: "memory");
        else if (c == NCHUNK - 2)
            asm volatile("cp.async.wait_group 1;" ::: "memory");
        else
            asm volatile("cp.async.wait_group 0;" ::: "memory");
        __syncthreads();
        if (c + NSTAGE - 1 < NCHUNK) {
            issue(c + NSTAGE - 1);              // stage (c-1)&3: readers passed barrier
            asm volatile("cp.async.commit_group;" ::: "memory");
        }

        const uint32_t* buf = smu + (c & (NSTAGE - 1)) * STAGEU;
        const float* xs = (const float*)buf;
        const float* ws = (const float*)(buf + XTILE);
        #pragma unroll 4
        for (int kk = 0; kk < BK; kk++) {
            unsigned long long b2[4];
            #pragma unroll
            for (int j = 0; j < 4; j++)
                b2[j] = *(const unsigned long long*)(ws + kk * 128 + 2 * tx + 32 * j);
            unsigned long long a2[7];
            #pragma unroll
            for (int i = 0; i < 7; i++)
                a2[i] = pack_dup(xs[(7 * ty + i) * XTS + kk]);
            #pragma unroll
            for (int i = 0; i < 7; i++)
                #pragma unroll
                for (int j = 0; j < 4; j++)
                    asm("fma.rn.f32x2 %0, %1, %2, %0;"
                        : "+l"(acc[i][j]) : "l"(a2[i]), "l"(b2[j]));
        }
        // no bottom sync: top wait+sync of next iteration orders stage reuse
    }

    // ---- write logits (STG.64, coalesced); guard tail CTA ----
    #pragma unroll
    for (int i = 0; i < 7; i++) {
        int row = row0 + 7 * ty + i;
        if (row < N_TOK) {
            #pragma unroll
            for (int j = 0; j < 4; j++)
                *(unsigned long long*)(g_lg + (size_t)row * 128 + 2 * tx + 32 * j)
                    = acc[i][j];
        }
    }
}

// ---------------- epilogue: 1 row per warp, redux top-9, fast-exp softmaxes ----------------
__device__ __forceinline__ uint32_t redux_max(uint32_t v) {
    uint32_t r;
    asm("redux.sync.max.u32 %0, %1, 0xffffffff;" : "=r"(r) : "r"(v));
    return r;
}
__device__ __forceinline__ uint32_t ordkey(float f) {
    uint32_t u = __float_as_uint(f);
    return ((int)u < 0) ? ~u : (u | 0x80000000u);
}
__device__ __forceinline__ float ordinv(uint32_t k) {
    return __uint_as_float(((int)k < 0) ? (k ^ 0x80000000u) : ~k);
}
__device__ __forceinline__ float wsum(float v) {
    #pragma unroll
    for (int o = 16; o; o >>= 1) v += __shfl_xor_sync(0xffffffffu, v, o);
    return v;
}

extern "C" __global__ void __launch_bounds__(256)
epi_kernel(const float* __restrict__ br,  const float* __restrict__ bn,
           const float* __restrict__ neps, const float* __restrict__ gum,
           float* __restrict__ out)
{
    __shared__ float imp_s[64], load_s[64];
    const int tid = threadIdx.x;
    const int wid = tid >> 5;
    const int lane = tid & 31;
    if (tid < 64) { imp_s[tid] = 0.f; load_s[tid] = 0.f; }
    __syncthreads();

    const int e0 = lane, e1 = lane + 32;
    const int row = blockIdx.x * 8 + wid;       // 1 row per warp, grid 2048

    const float* L = g_lg + (size_t)row * 128;
    float raw0 = L[e0] + br[e0],      raw1 = L[e1] + br[e1];
    float pre0 = L[64 + e0] + bn[e0], pre1 = L[64 + e1] + bn[e1];
    // softplus kept at full precision: feeds noisy logits -> top-k selection
    float sd0 = fmaxf(pre0, 0.f) + log1pf(expf(-fabsf(pre0))) + EPS_C;
    float sd1 = fmaxf(pre1, 0.f) + log1pf(expf(-fabsf(pre1))) + EPS_C;
    float nz0 = fmaf(neps[(size_t)row * NEXP + e0], sd0, raw0);
    float nz1 = fmaf(neps[(size_t)row * NEXP + e1], sd1, raw1);
    float g0 = gum[(size_t)row * NEXP + e0];
    float g1 = gum[(size_t)row * NEXP + e1];

    // ---- top-9 via redux.max on orderable keys (exact, tie -> lowest idx) ----
    uint32_t k0 = ordkey(nz0), k1 = ordkey(nz1);
    float h0 = 0.f, h1 = 0.f, thr = 0.f, m1 = 0.f;
    #pragma unroll 1
    for (int t = 0; t < KSEL; t++) {
        uint32_t M = redux_max(k0 > k1 ? k0 : k1);
        if (t == 0) m1 = ordinv(M);
        thr = ordinv(M);
        unsigned b0 = __ballot_sync(0xffffffffu, k0 == M);
        unsigned b1 = __ballot_sync(0xffffffffu, k1 == M);
        if (b0) {
            if (lane == __ffs(b0) - 1) { h0 = 1.f; k0 = 0u; }
        } else {
            if (lane == __ffs(b1) - 1) { h1 = 1.f; k1 = 0u; }
        }
    }

    // ---- softmax maxes via redux; exps via fast MUFU path (continuous outputs only) ----
    float m2 = ordinv(redux_max(ordkey(fmaxf(nz0 + g0, nz1 + g1))));
    float m3 = ordinv(redux_max(ordkey(fmaxf(raw0, raw1))));
    float E10 = __expf(nz0 - m1),      E11 = __expf(nz1 - m1);
    float E20 = __expf(nz0 + g0 - m2), E21 = __expf(nz1 + g1 - m2);
    float E30 = __expf(raw0 - m3),     E31 = __expf(raw1 - m3);
    float i1 = 1.f / wsum(E10 + E11);
    float i2 = 1.f / wsum(E20 + E21);
    float i3 = 1.f / wsum(E30 + E31);

    float ms0 = E20 * i2, ms1 = E21 * i2;
    float* om  = out + (size_t)row * NEXP;
    float* orp = out + (size_t)N_TOK * NEXP + (size_t)row * NEXP;
    om[e0]  = (h0 - ms0) + ms0;
    om[e1]  = (h1 - ms1) + ms1;
    orp[e0] = E10 * i1;
    orp[e1] = E11 * i1;

    float imp0 = E30 * i3, imp1 = E31 * i3;
    // erf kept exact: 45x slope on the load output
    float z0 = (thr - raw0) / sd0, z1 = (thr - raw1) / sd1;
    float ld0 = 0.5f * (1.f - erff(z0 * INV_SIG_SQRT2));
    float ld1 = 0.5f * (1.f - erff(z1 * INV_SIG_SQRT2));

    atomicAdd(&imp_s[e0], imp0);
    atomicAdd(&imp_s[e1], imp1);
    atomicAdd(&load_s[e0], ld0);
    atomicAdd(&load_s[e1], ld1);
    __syncthreads();
    if (tid < 64) {
        atomicAdd(out + 2 * (size_t)N_TOK * NEXP + tid,        imp_s[tid]);
        atomicAdd(out + 2 * (size_t)N_TOK * NEXP + NEXP + tid, load_s[tid]);
    }
}

extern "C" void kernel_launch(void* const* d_in, const int* in_sizes, int n_in,
                              void* d_out, int out_size)
{
    const float* x    = (const float*)d_in[0];
    const float* Wr   = (const float*)d_in[1];
    const float* br   = (const float*)d_in[2];
    const float* Wn   = (const float*)d_in[3];
    const float* bn   = (const float*)d_in[4];
    const float* neps = (const float*)d_in[5];
    const float* gum  = (const float*)d_in[6];
    float* out = (float*)d_out;

    cudaMemsetAsync(out + 2 * (size_t)N_TOK * NEXP, 0, 2 * NEXP * sizeof(float));

    cudaFuncSetAttribute(gemm_kernel,
                         cudaFuncAttributeMaxDynamicSharedMemorySize, SMEM_BYTES);
    gemm_kernel<<<GRID, 256, SMEM_BYTES>>>(x, Wr, Wn);

    epi_kernel<<<N_TOK / 8, 256>>>(br, bn, neps, gum, out);
}

// round 14
// speedup vs baseline: 1.1946x; 1.0005x over previous
#include <cuda_runtime.h>
#include <math.h>
#include <stdint.h>

#define N_TOK 16384
#define DIM   2048
#define NEXP  64
#define KSEL  9
#define EPS_C 0.01f
#define INV_SIG_SQRT2 45.254833995939045f

#define BM 112
#define GRID 147                   // ceil(16384/112)
#define BK 32
#define NCHUNK (DIM / BK)          // 64
#define NSTAGE 4
#define XTS 36                     // x smem row stride (u32)
#define XTILE (BM * XTS)           // 4032 u32
#define WTILE (BK * 128)           // 4096 u32
#define STAGEU (XTILE + WTILE)     // 8128 u32 = 32512 B
#define SMEM_BYTES (NSTAGE * STAGEU * 4)   // 130048 B
#define XV4 (BM * 8)               // 896 float4 per x stage

// logits scratch: [row][128] (0-63 raw dot, 64-127 noise-pre dot) = 8 MB
__device__ __align__(16) float g_lg[(size_t)N_TOK * 128];

__device__ __forceinline__ unsigned long long pack_dup(float a) {
    unsigned long long r;
    unsigned ai = __float_as_uint(a);
    asm("mov.b64 %0, {%1, %1};" : "=l"(r) : "r"(ai));
    return r;
}
__device__ __forceinline__ uint32_t smem_u32(const void* p) {
    uint32_t a;
    asm("{ .reg .u64 t; cvta.to.shared.u64 t, %1; cvt.u32.u64 %0, t; }"
        : "=r"(a) : "l"(p));
    return a;
}
__device__ __forceinline__ void cp16(uint32_t dst, const void* src) {
    asm volatile("cp.async.ca.shared.global [%0], [%1], 16;"
                 :: "r"(dst), "l"(src) : "memory");
}

// ---------------- GEMM: fp32 FFMA2, 112x128 per CTA, 147 CTAs (1/SM) ----------------
// (round-8 proven configuration — FROZEN; only addition: CTA 0 zeroes reduction bins)
extern "C" __global__ void __launch_bounds__(256, 1)
gemm_kernel(const float* __restrict__ x, const float* __restrict__ Wr,
            const float* __restrict__ Wn, float* __restrict__ out)
{
    extern __shared__ uint32_t smu[];
    const uint32_t sbase = smem_u32(smu);
    const int tid = threadIdx.x;
    const int ty  = tid >> 4;        // 0..15 -> rows 7ty..7ty+6
    const int tx  = tid & 15;        // col pairs 2tx+32j
    const int row0 = blockIdx.x * BM;

    // zero the importance/load accumulator region (epi runs strictly after gemm)
    if (blockIdx.x == 0 && tid < 2 * NEXP)
        out[2 * (size_t)N_TOK * NEXP + tid] = 0.f;

    // ---- x cp.async map: 896 float4 over 256 threads x 4 iters (guarded) ----
    const float* xsrc[4];
    uint32_t     xoff[4];
    bool         xact[4];
    #pragma unroll
    for (int i = 0; i < 4; i++) {
        int idx = tid + 256 * i;
        xact[i] = (idx < XV4);
        int r = idx >> 3, seg = idx & 7;
        if (!xact[i]) { r = 0; seg = 0; }
        int grow = row0 + r; if (grow > N_TOK - 1) grow = N_TOK - 1;  // tail clamp
        xsrc[i] = x + (size_t)grow * DIM + seg * 4;
        xoff[i] = (uint32_t)((r * XTS + seg * 4) * 4);
    }
    // ---- W cp.async map ----
    const int wk = tid >> 5, wq = tid & 31;
    const int wcol = wq * 4;
    const float* wsrcbase = (wcol < 64) ? (Wr + wcol) : (Wn + wcol - 64);

    unsigned long long acc[7][4];
    #pragma unroll
    for (int i = 0; i < 7; i++)
        #pragma unroll
        for (int j = 0; j < 4; j++) acc[i][j] = 0ULL;

    auto issue = [&](int c) {
        uint32_t buf = sbase + (uint32_t)((c & (NSTAGE - 1)) * STAGEU * 4);
        #pragma unroll
        for (int i = 0; i < 4; i++)
            if (xact[i]) cp16(buf + xoff[i], xsrc[i] + c * BK);
        #pragma unroll
        for (int i = 0; i < 4; i++) {
            int kk = wk + 8 * i;
            cp16(buf + (uint32_t)((XTILE + kk * 128 + wcol) * 4),
                 wsrcbase + (size_t)(c * BK + kk) * NEXP);
        }
    };

    // prologue: stages 0..2
    #pragma unroll
    for (int p = 0; p < NSTAGE - 1; p++) {
        issue(p);
        asm volatile("cp.async.commit_group;" ::: "memory");
    }

    #pragma unroll 1
    for (int c = 0; c < NCHUNK; c++) {
        // peeled waits: per-thread pending groups shrink at the tail
        if (c < NCHUNK - 2)
            asm volatile("cp.async.wait_group 2;" ::: "memory");
        else if (c == NCHUNK - 2)
            asm volatile("cp.async.wait_group 1;" ::: "memory");
        else
            asm volatile("cp.async.wait_group 0;" ::: "memory");
        __syncthreads();
        if (c + NSTAGE - 1 < NCHUNK) {
            issue(c + NSTAGE - 1);              // stage (c-1)&3: readers passed barrier
            asm volatile("cp.async.commit_group;" ::: "memory");
        }

        const uint32_t* buf = smu + (c & (NSTAGE - 1)) * STAGEU;
        const float* xs = (const float*)buf;
        const float* ws = (const float*)(buf + XTILE);
        #pragma unroll 4
        for (int kk = 0; kk < BK; kk++) {
            unsigned long long b2[4];
            #pragma unroll
            for (int j = 0; j < 4; j++)
                b2[j] = *(const unsigned long long*)(ws + kk * 128 + 2 * tx + 32 * j);
            unsigned long long a2[7];
            #pragma unroll
            for (int i = 0; i < 7; i++)
                a2[i] = pack_dup(xs[(7 * ty + i) * XTS + kk]);
            #pragma unroll
            for (int i = 0; i < 7; i++)
                #pragma unroll
                for (int j = 0; j < 4; j++)
                    asm("fma.rn.f32x2 %0, %1, %2, %0;"
                        : "+l"(acc[i][j]) : "l"(a2[i]), "l"(b2[j]));
        }
        // no bottom sync: top wait+sync of next iteration orders stage reuse
    }

    // ---- write logits (STG.64, coalesced); guard tail CTA ----
    #pragma unroll
    for (int i = 0; i < 7; i++) {
        int row = row0 + 7 * ty + i;
        if (row < N_TOK) {
            #pragma unroll
            for (int j = 0; j < 4; j++)
                *(unsigned long long*)(g_lg + (size_t)row * 128 + 2 * tx + 32 * j)
                    = acc[i][j];
        }
    }
}

// ---------------- epilogue: 1 row per warp, redux top-9, fast exp/rcp ----------------
__device__ __forceinline__ uint32_t redux_max(uint32_t v) {
    uint32_t r;
    asm("redux.sync.max.u32 %0, %1, 0xffffffff;" : "=r"(r) : "r"(v));
    return r;
}
__device__ __forceinline__ uint32_t ordkey(float f) {
    uint32_t u = __float_as_uint(f);
    return ((int)u < 0) ? ~u : (u | 0x80000000u);
}
__device__ __forceinline__ float ordinv(uint32_t k) {
    return __uint_as_float(((int)k < 0) ? (k ^ 0x80000000u) : ~k);
}
__device__ __forceinline__ float wsum(float v) {
    #pragma unroll
    for (int o = 16; o; o >>= 1) v += __shfl_xor_sync(0xffffffffu, v, o);
    return v;
}

extern "C" __global__ void __launch_bounds__(256)
epi_kernel(const float* __restrict__ br,  const float* __restrict__ bn,
           const float* __restrict__ neps, const float* __restrict__ gum,
           float* __restrict__ out)
{
    __shared__ float imp_s[64], load_s[64];
    const int tid = threadIdx.x;
    const int wid = tid >> 5;
    const int lane = tid & 31;
    if (tid < 64) { imp_s[tid] = 0.f; load_s[tid] = 0.f; }
    __syncthreads();

    const int e0 = lane, e1 = lane + 32;
    const int row = blockIdx.x * 8 + wid;       // 1 row per warp, grid 2048

    const float* L = g_lg + (size_t)row * 128;
    float raw0 = L[e0] + br[e0],      raw1 = L[e1] + br[e1];
    float pre0 = L[64 + e0] + bn[e0], pre1 = L[64 + e1] + bn[e1];
    // softplus kept at full precision: feeds noisy logits -> top-k selection
    float sd0 = fmaxf(pre0, 0.f) + log1pf(expf(-fabsf(pre0))) + EPS_C;
    float sd1 = fmaxf(pre1, 0.f) + log1pf(expf(-fabsf(pre1))) + EPS_C;
    float nz0 = fmaf(neps[(size_t)row * NEXP + e0], sd0, raw0);
    float nz1 = fmaf(neps[(size_t)row * NEXP + e1], sd1, raw1);
    float g0 = gum[(size_t)row * NEXP + e0];
    float g1 = gum[(size_t)row * NEXP + e1];

    // ---- top-9 via redux.max on orderable keys (exact, tie -> lowest idx) ----
    uint32_t k0 = ordkey(nz0), k1 = ordkey(nz1);
    float h0 = 0.f, h1 = 0.f, thr = 0.f, m1 = 0.f;
    #pragma unroll 1
    for (int t = 0; t < KSEL; t++) {
        uint32_t M = redux_max(k0 > k1 ? k0 : k1);
        if (t == 0) m1 = ordinv(M);
        thr = ordinv(M);
        unsigned b0 = __ballot_sync(0xffffffffu, k0 == M);
        unsigned b1 = __ballot_sync(0xffffffffu, k1 == M);
        if (b0) {
            if (lane == __ffs(b0) - 1) { h0 = 1.f; k0 = 0u; }
        } else {
            if (lane == __ffs(b1) - 1) { h1 = 1.f; k1 = 0u; }
        }
    }

    // ---- softmax maxes via redux; fast exp/rcp (continuous outputs only) ----
    float m2 = ordinv(redux_max(ordkey(fmaxf(nz0 + g0, nz1 + g1))));
    float m3 = ordinv(redux_max(ordkey(fmaxf(raw0, raw1))));
    float E10 = __expf(nz0 - m1),      E11 = __expf(nz1 - m1);
    float E20 = __expf(nz0 + g0 - m2), E21 = __expf(nz1 + g1 - m2);
    float E30 = __expf(raw0 - m3),     E31 = __expf(raw1 - m3);
    float i1 = __fdividef(1.f, wsum(E10 + E11));
    float i2 = __fdividef(1.f, wsum(E20 + E21));   // cancels in expert_mask
    float i3 = __fdividef(1.f, wsum(E30 + E31));

    float ms0 = E20 * i2, ms1 = E21 * i2;
    float* om  = out + (size_t)row * NEXP;
    float* orp = out + (size_t)N_TOK * NEXP + (size_t)row * NEXP;
    om[e0]  = (h0 - ms0) + ms0;
    om[e1]  = (h1 - ms1) + ms1;
    orp[e0] = E10 * i1;
    orp[e1] = E11 * i1;

    float imp0 = E30 * i3, imp1 = E31 * i3;
    // erf kept exact: 45x slope on the load output
    float z0 = (thr - raw0) / sd0, z1 = (thr - raw1) / sd1;
    float ld0 = 0.5f * (1.f - erff(z0 * INV_SIG_SQRT2));
    float ld1 = 0.5f * (1.f - erff(z1 * INV_SIG_SQRT2));

    atomicAdd(&imp_s[e0], imp0);
    atomicAdd(&imp_s[e1], imp1);
    atomicAdd(&load_s[e0], ld0);
    atomicAdd(&load_s[e1], ld1);
    __syncthreads();
    if (tid < 64) {
        atomicAdd(out + 2 * (size_t)N_TOK * NEXP + tid,        imp_s[tid]);
        atomicAdd(out + 2 * (size_t)N_TOK * NEXP + NEXP + tid, load_s[tid]);
    }
}

extern "C" void kernel_launch(void* const* d_in, const int* in_sizes, int n_in,
                              void* d_out, int out_size)
{
    const float* x    = (const float*)d_in[0];
    const float* Wr   = (const float*)d_in[1];
    const float* br   = (const float*)d_in[2];
    const float* Wn   = (const float*)d_in[3];
    const float* bn   = (const float*)d_in[4];
    const float* neps = (const float*)d_in[5];
    const float* gum  = (const float*)d_in[6];
    float* out = (float*)d_out;

    cudaFuncSetAttribute(gemm_kernel,
                         cudaFuncAttributeMaxDynamicSharedMemorySize, SMEM_BYTES);
    gemm_kernel<<<GRID, 256, SMEM_BYTES>>>(x, Wr, Wn, out);

    epi_kernel<<<N_TOK / 8, 256>>>(br, bn, neps, gum, out);
}

// round 15
// speedup vs baseline: 1.1999x; 1.0044x over previous
#include <cuda_runtime.h>
#include <math.h>
#include <stdint.h>

#define N_TOK 16384
#define DIM   2048
#define NEXP  64
#define KSEL  9
#define EPS_C 0.01f
#define INV_SIG_SQRT2 45.254833995939045f

#define BM 112
#define GRID 147                   // ceil(16384/112)
#define BK 32
#define NCHUNK (DIM / BK)          // 64
#define NSTAGE 4
#define XTS 36                     // x smem row stride (u32)
#define XTILE (BM * XTS)           // 4032 u32
#define WTILE (BK * 128)           // 4096 u32
#define STAGEU (XTILE + WTILE)     // 8128 u32 = 32512 B
#define SMEM_BYTES (NSTAGE * STAGEU * 4)   // 130048 B
#define XV4 (BM * 8)               // 896 float4 per x stage

// logits scratch: [row][128] (0-63 raw dot, 64-127 noise-pre dot) = 8 MB
__device__ __align__(16) float g_lg[(size_t)N_TOK * 128];

__device__ __forceinline__ unsigned long long pack_dup(float a) {
    unsigned long long r;
    unsigned ai = __float_as_uint(a);
    asm("mov.b64 %0, {%1, %1};" : "=l"(r) : "r"(ai));
    return r;
}
__device__ __forceinline__ uint32_t smem_u32(const void* p) {
    uint32_t a;
    asm("{ .reg .u64 t; cvta.to.shared.u64 t, %1; cvt.u32.u64 %0, t; }"
        : "=r"(a) : "l"(p));
    return a;
}
// .cg: bypass L1 (x has no L1 reuse; W reuse is cross-CTA via L2).
// Removes L1-allocation wavefronts contending with mainloop LDS on L1TEX.
__device__ __forceinline__ void cp16(uint32_t dst, const void* src) {
    asm volatile("cp.async.cg.shared.global [%0], [%1], 16;"
                 :: "r"(dst), "l"(src) : "memory");
}

// ---------------- GEMM: fp32 FFMA2, 112x128 per CTA, 147 CTAs (1/SM) ----------------
// (round-8 proven configuration — FROZEN except cp.async cache hint)
extern "C" __global__ void __launch_bounds__(256, 1)
gemm_kernel(const float* __restrict__ x, const float* __restrict__ Wr,
            const float* __restrict__ Wn, float* __restrict__ out)
{
    extern __shared__ uint32_t smu[];
    const uint32_t sbase = smem_u32(smu);
    const int tid = threadIdx.x;
    const int ty  = tid >> 4;        // 0..15 -> rows 7ty..7ty+6
    const int tx  = tid & 15;        // col pairs 2tx+32j
    const int row0 = blockIdx.x * BM;

    // zero the importance/load accumulator region (epi runs strictly after gemm)
    if (blockIdx.x == 0 && tid < 2 * NEXP)
        out[2 * (size_t)N_TOK * NEXP + tid] = 0.f;

    // ---- x cp.async map: 896 float4 over 256 threads x 4 iters (guarded) ----
    const float* xsrc[4];
    uint32_t     xoff[4];
    bool         xact[4];
    #pragma unroll
    for (int i = 0; i < 4; i++) {
        int idx = tid + 256 * i;
        xact[i] = (idx < XV4);
        int r = idx >> 3, seg = idx & 7;
        if (!xact[i]) { r = 0; seg = 0; }
        int grow = row0 + r; if (grow > N_TOK - 1) grow = N_TOK - 1;  // tail clamp
        xsrc[i] = x + (size_t)grow * DIM + seg * 4;
        xoff[i] = (uint32_t)((r * XTS + seg * 4) * 4);
    }
    // ---- W cp.async map ----
    const int wk = tid >> 5, wq = tid & 31;
    const int wcol = wq * 4;
    const float* wsrcbase = (wcol < 64) ? (Wr + wcol) : (Wn + wcol - 64);

    unsigned long long acc[7][4];
    #pragma unroll
    for (int i = 0; i < 7; i++)
        #pragma unroll
        for (int j = 0; j < 4; j++) acc[i][j] = 0ULL;

    auto issue = [&](int c) {
        uint32_t buf = sbase + (uint32_t)((c & (NSTAGE - 1)) * STAGEU * 4);
        #pragma unroll
        for (int i = 0; i < 4; i++)
            if (xact[i]) cp16(buf + xoff[i], xsrc[i] + c * BK);
        #pragma unroll
        for (int i = 0; i < 4; i++) {
            int kk = wk + 8 * i;
            cp16(buf + (uint32_t)((XTILE + kk * 128 + wcol) * 4),
                 wsrcbase + (size_t)(c * BK + kk) * NEXP);
        }
    };

    // prologue: stages 0..2
    #pragma unroll
    for (int p = 0; p < NSTAGE - 1; p++) {
        issue(p);
        asm volatile("cp.async.commit_group;" ::: "memory");
    }

    #pragma unroll 1
    for (int c = 0; c < NCHUNK; c++) {
        // peeled waits: per-thread pending groups shrink at the tail
        if (c < NCHUNK - 2)
            asm volatile("cp.async.wait_group 2;" ::: "memory");
        else if (c == NCHUNK - 2)
            asm volatile("cp.async.wait_group 1;" ::: "memory");
        else
            asm volatile("cp.async.wait_group 0;" ::: "memory");
        __syncthreads();
        if (c + NSTAGE - 1 < NCHUNK) {
            issue(c + NSTAGE - 1);              // stage (c-1)&3: readers passed barrier
            asm volatile("cp.async.commit_group;" ::: "memory");
        }

        const uint32_t* buf = smu + (c & (NSTAGE - 1)) * STAGEU;
        const float* xs = (const float*)buf;
        const float* ws = (const float*)(buf + XTILE);
        #pragma unroll 4
        for (int kk = 0; kk < BK; kk++) {
            unsigned long long b2[4];
            #pragma unroll
            for (int j = 0; j < 4; j++)
                b2[j] = *(const unsigned long long*)(ws + kk * 128 + 2 * tx + 32 * j);
            unsigned long long a2[7];
            #pragma unroll
            for (int i = 0; i < 7; i++)
                a2[i] = pack_dup(xs[(7 * ty + i) * XTS + kk]);
            #pragma unroll
            for (int i = 0; i < 7; i++)
                #pragma unroll
                for (int j = 0; j < 4; j++)
                    asm("fma.rn.f32x2 %0, %1, %2, %0;"
                        : "+l"(acc[i][j]) : "l"(a2[i]), "l"(b2[j]));
        }
        // no bottom sync: top wait+sync of next iteration orders stage reuse
    }

    // ---- write logits (STG.64, coalesced); guard tail CTA ----
    #pragma unroll
    for (int i = 0; i < 7; i++) {
        int row = row0 + 7 * ty + i;
        if (row < N_TOK) {
            #pragma unroll
            for (int j = 0; j < 4; j++)
                *(unsigned long long*)(g_lg + (size_t)row * 128 + 2 * tx + 32 * j)
                    = acc[i][j];
        }
    }
}

// ---------------- epilogue: 1 row per warp, redux top-9, fast exp/rcp ----------------
__device__ __forceinline__ uint32_t redux_max(uint32_t v) {
    uint32_t r;
    asm("redux.sync.max.u32 %0, %1, 0xffffffff;" : "=r"(r) : "r"(v));
    return r;
}
__device__ __forceinline__ uint32_t ordkey(float f) {
    uint32_t u = __float_as_uint(f);
    return ((int)u < 0) ? ~u : (u | 0x80000000u);
}
__device__ __forceinline__ float ordinv(uint32_t k) {
    return __uint_as_float(((int)k < 0) ? (k ^ 0x80000000u) : ~k);
}
__device__ __forceinline__ float wsum(float v) {
    #pragma unroll
    for (int o = 16; o; o >>= 1) v += __shfl_xor_sync(0xffffffffu, v, o);
    return v;
}

extern "C" __global__ void __launch_bounds__(256)
epi_kernel(const float* __restrict__ br,  const float* __restrict__ bn,
           const float* __restrict__ neps, const float* __restrict__ gum,
           float* __restrict__ out)
{
    __shared__ float imp_s[64], load_s[64];
    const int tid = threadIdx.x;
    const int wid = tid >> 5;
    const int lane = tid & 31;
    if (tid < 64) { imp_s[tid] = 0.f; load_s[tid] = 0.f; }
    __syncthreads();

    const int e0 = lane, e1 = lane + 32;
    const int row = blockIdx.x * 8 + wid;       // 1 row per warp, grid 2048

    const float* L = g_lg + (size_t)row * 128;
    float raw0 = L[e0] + br[e0],      raw1 = L[e1] + br[e1];
    float pre0 = L[64 + e0] + bn[e0], pre1 = L[64 + e1] + bn[e1];
    // softplus kept at full precision: feeds noisy logits -> top-k selection
    float sd0 = fmaxf(pre0, 0.f) + log1pf(expf(-fabsf(pre0))) + EPS_C;
    float sd1 = fmaxf(pre1, 0.f) + log1pf(expf(-fabsf(pre1))) + EPS_C;
    float nz0 = fmaf(neps[(size_t)row * NEXP + e0], sd0, raw0);
    float nz1 = fmaf(neps[(size_t)row * NEXP + e1], sd1, raw1);
    float g0 = gum[(size_t)row * NEXP + e0];
    float g1 = gum[(size_t)row * NEXP + e1];

    // ---- top-9 via redux.max on orderable keys (exact, tie -> lowest idx) ----
    uint32_t k0 = ordkey(nz0), k1 = ordkey(nz1);
    float h0 = 0.f, h1 = 0.f, thr = 0.f, m1 = 0.f;
    #pragma unroll 1
    for (int t = 0; t < KSEL; t++) {
        uint32_t M = redux_max(k0 > k1 ? k0 : k1);
        if (t == 0) m1 = ordinv(M);
        thr = ordinv(M);
        unsigned b0 = __ballot_sync(0xffffffffu, k0 == M);
        if (b0) {                                // warp-uniform branch
            if (lane == __ffs(b0) - 1) { h0 = 1.f; k0 = 0u; }
        } else {
            unsigned b1 = __ballot_sync(0xffffffffu, k1 == M);
            if (lane == __ffs(b1) - 1) { h1 = 1.f; k1 = 0u; }
        }
    }

    // ---- softmax maxes via redux; fast exp/rcp (continuous outputs only) ----
    float m2 = ordinv(redux_max(ordkey(fmaxf(nz0 + g0, nz1 + g1))));
    float m3 = ordinv(redux_max(ordkey(fmaxf(raw0, raw1))));
    float E10 = __expf(nz0 - m1),      E11 = __expf(nz1 - m1);
    float E20 = __expf(nz0 + g0 - m2), E21 = __expf(nz1 + g1 - m2);
    float E30 = __expf(raw0 - m3),     E31 = __expf(raw1 - m3);
    float i1 = __fdividef(1.f, wsum(E10 + E11));
    float i2 = __fdividef(1.f, wsum(E20 + E21));   // cancels in expert_mask
    float i3 = __fdividef(1.f, wsum(E30 + E31));

    float ms0 = E20 * i2, ms1 = E21 * i2;
    float* om  = out + (size_t)row * NEXP;
    float* orp = out + (size_t)N_TOK * NEXP + (size_t)row * NEXP;
    om[e0]  = (h0 - ms0) + ms0;
    om[e1]  = (h1 - ms1) + ms1;
    orp[e0] = E10 * i1;
    orp[e1] = E11 * i1;

    float imp0 = E30 * i3, imp1 = E31 * i3;
    // erf kept exact: 45x slope on the load output
    float z0 = (thr - raw0) / sd0, z1 = (thr - raw1) / sd1;
    float ld0 = 0.5f * (1.f - erff(z0 * INV_SIG_SQRT2));
    float ld1 = 0.5f * (1.f - erff(z1 * INV_SIG_SQRT2));

    atomicAdd(&imp_s[e0], imp0);
    atomicAdd(&imp_s[e1], imp1);
    atomicAdd(&load_s[e0], ld0);
    atomicAdd(&load_s[e1], ld1);
    __syncthreads();
    if (tid < 64) {
        atomicAdd(out + 2 * (size_t)N_TOK * NEXP + tid,        imp_s[tid]);
        atomicAdd(out + 2 * (size_t)N_TOK * NEXP + NEXP + tid, load_s[tid]);
    }
}

extern "C" void kernel_launch(void* const* d_in, const int* in_sizes, int n_in,
                              void* d_out, int out_size)
{
    const float* x    = (const float*)d_in[0];
    const float* Wr   = (const float*)d_in[1];
    const float* br   = (const float*)d_in[2];
    const float* Wn   = (const float*)d_in[3];
    const float* bn   = (const float*)d_in[4];
    const float* neps = (const float*)d_in[5];
    const float* gum  = (const float*)d_in[6];
    float* out = (float*)d_out;

    cudaFuncSetAttribute(gemm_kernel,
                         cudaFuncAttributeMaxDynamicSharedMemorySize, SMEM_BYTES);
    gemm_kernel<<<GRID, 256, SMEM_BYTES>>>(x, Wr, Wn, out);

    epi_kernel<<<N_TOK / 8, 256>>>(br, bn, neps, gum, out);
}

// round 16
// speedup vs baseline: 1.2135x; 1.0113x over previous
#include <cuda_runtime.h>
#include <math.h>
#include <stdint.h>

#define N_TOK 16384
#define DIM   2048
#define NEXP  64
#define KSEL  9
#define EPS_C 0.01f
#define INV_SIG_SQRT2 45.254833995939045f

#define BM 112
#define GRID 147                   // ceil(16384/112)
#define BK 32
#define NCHUNK (DIM / BK)          // 64
#define NSTAGE 4
#define XTS 36                     // x smem row stride (u32)
#define XTILE (BM * XTS)           // 4032 u32
#define WTILE (BK * 128)           // 4096 u32
#define STAGEU (XTILE + WTILE)     // 8128 u32 = 32512 B
#define SMEM_BYTES (NSTAGE * STAGEU * 4)   // 130048 B
#define XV4 (BM * 8)               // 896 float4 per x stage

// logits scratch: [row][128] (0-63 raw dot, 64-127 noise-pre dot) = 8 MB
__device__ __align__(16) float g_lg[(size_t)N_TOK * 128];

__device__ __forceinline__ unsigned long long pack_dup(float a) {
    unsigned long long r;
    unsigned ai = __float_as_uint(a);
    asm("mov.b64 %0, {%1, %1};" : "=l"(r) : "r"(ai));
    return r;
}
__device__ __forceinline__ uint32_t smem_u32(const void* p) {
    uint32_t a;
    asm("{ .reg .u64 t; cvta.to.shared.u64 t, %1; cvt.u32.u64 %0, t; }"
        : "=r"(a) : "l"(p));
    return a;
}
// .cg: bypass L1 (x has no L1 reuse; W reuse is cross-CTA via L2).
__device__ __forceinline__ void cp16(uint32_t dst, const void* src) {
    asm volatile("cp.async.cg.shared.global [%0], [%1], 16;"
                 :: "r"(dst), "l"(src) : "memory");
}

// ---------------- GEMM: fp32 FFMA2, 112x128 per CTA, 147 CTAs (1/SM) ----------------
// (round-15 proven configuration — FROZEN)
extern "C" __global__ void __launch_bounds__(256, 1)
gemm_kernel(const float* __restrict__ x, const float* __restrict__ Wr,
            const float* __restrict__ Wn, float* __restrict__ out)
{
    extern __shared__ uint32_t smu[];
    const uint32_t sbase = smem_u32(smu);
    const int tid = threadIdx.x;
    const int ty  = tid >> 4;        // 0..15 -> rows 7ty..7ty+6
    const int tx  = tid & 15;        // col pairs 2tx+32j
    const int row0 = blockIdx.x * BM;

    // zero the importance/load accumulator region (epi runs strictly after gemm)
    if (blockIdx.x == 0 && tid < 2 * NEXP)
        out[2 * (size_t)N_TOK * NEXP + tid] = 0.f;

    // ---- x cp.async map: 896 float4 over 256 threads x 4 iters (guarded) ----
    const float* xsrc[4];
    uint32_t     xoff[4];
    bool         xact[4];
    #pragma unroll
    for (int i = 0; i < 4; i++) {
        int idx = tid + 256 * i;
        xact[i] = (idx < XV4);
        int r = idx >> 3, seg = idx & 7;
        if (!xact[i]) { r = 0; seg = 0; }
        int grow = row0 + r; if (grow > N_TOK - 1) grow = N_TOK - 1;  // tail clamp
        xsrc[i] = x + (size_t)grow * DIM + seg * 4;
        xoff[i] = (uint32_t)((r * XTS + seg * 4) * 4);
    }
    // ---- W cp.async map ----
    const int wk = tid >> 5, wq = tid & 31;
    const int wcol = wq * 4;
    const float* wsrcbase = (wcol < 64) ? (Wr + wcol) : (Wn + wcol - 64);

    unsigned long long acc[7][4];
    #pragma unroll
    for (int i = 0; i < 7; i++)
        #pragma unroll
        for (int j = 0; j < 4; j++) acc[i][j] = 0ULL;

    auto issue = [&](int c) {
        uint32_t buf = sbase + (uint32_t)((c & (NSTAGE - 1)) * STAGEU * 4);
        #pragma unroll
        for (int i = 0; i < 4; i++)
            if (xact[i]) cp16(buf + xoff[i], xsrc[i] + c * BK);
        #pragma unroll
        for (int i = 0; i < 4; i++) {
            int kk = wk + 8 * i;
            cp16(buf + (uint32_t)((XTILE + kk * 128 + wcol) * 4),
                 wsrcbase + (size_t)(c * BK + kk) * NEXP);
        }
    };

    // prologue: stages 0..2
    #pragma unroll
    for (int p = 0; p < NSTAGE - 1; p++) {
        issue(p);
        asm volatile("cp.async.commit_group;" ::: "memory");
    }

    #pragma unroll 1
    for (int c = 0; c < NCHUNK; c++) {
        if (c < NCHUNK - 2)
            asm volatile("cp.async.wait_group 2;" ::: "memory");
        else if (c == NCHUNK - 2)
            asm volatile("cp.async.wait_group 1;" ::: "memory");
        else
            asm volatile("cp.async.wait_group 0;" ::: "memory");
        __syncthreads();
        if (c + NSTAGE - 1 < NCHUNK) {
            issue(c + NSTAGE - 1);              // stage (c-1)&3: readers passed barrier
            asm volatile("cp.async.commit_group;" ::: "memory");
        }

        const uint32_t* buf = smu + (c & (NSTAGE - 1)) * STAGEU;
        const float* xs = (const float*)buf;
        const float* ws = (const float*)(buf + XTILE);
        #pragma unroll 4
        for (int kk = 0; kk < BK; kk++) {
            unsigned long long b2[4];
            #pragma unroll
            for (int j = 0; j < 4; j++)
                b2[j] = *(const unsigned long long*)(ws + kk * 128 + 2 * tx + 32 * j);
            unsigned long long a2[7];
            #pragma unroll
            for (int i = 0; i < 7; i++)
                a2[i] = pack_dup(xs[(7 * ty + i) * XTS + kk]);
            #pragma unroll
            for (int i = 0; i < 7; i++)
                #pragma unroll
                for (int j = 0; j < 4; j++)
                    asm("fma.rn.f32x2 %0, %1, %2, %0;"
                        : "+l"(acc[i][j]) : "l"(a2[i]), "l"(b2[j]));
        }
    }

    // ---- write logits (STG.64, coalesced); guard tail CTA ----
    #pragma unroll
    for (int i = 0; i < 7; i++) {
        int row = row0 + 7 * ty + i;
        if (row < N_TOK) {
            #pragma unroll
            for (int j = 0; j < 4; j++)
                *(unsigned long long*)(g_lg + (size_t)row * 128 + 2 * tx + 32 * j)
                    = acc[i][j];
        }
    }
}

// ---------------- epilogue: 2 rows per warp INTERLEAVED (latency hiding) ----------------
__device__ __forceinline__ uint32_t redux_max(uint32_t v) {
    uint32_t r;
    asm("redux.sync.max.u32 %0, %1, 0xffffffff;" : "=r"(r) : "r"(v));
    return r;
}
__device__ __forceinline__ uint32_t ordkey(float f) {
    uint32_t u = __float_as_uint(f);
    return ((int)u < 0) ? ~u : (u | 0x80000000u);
}
__device__ __forceinline__ float ordinv(uint32_t k) {
    return __uint_as_float(((int)k < 0) ? (k ^ 0x80000000u) : ~k);
}
__device__ __forceinline__ void wsum2(float& a, float& b) {
    #pragma unroll
    for (int o = 16; o; o >>= 1) {
        a += __shfl_xor_sync(0xffffffffu, a, o);
        b += __shfl_xor_sync(0xffffffffu, b, o);
    }
}

extern "C" __global__ void __launch_bounds__(256)
epi_kernel(const float* __restrict__ br,  const float* __restrict__ bn,
           const float* __restrict__ neps, const float* __restrict__ gum,
           float* __restrict__ out)
{
    __shared__ float imp_s[64], load_s[64];
    const int tid = threadIdx.x;
    const int wid = tid >> 5;
    const int lane = tid & 31;
    if (tid < 64) { imp_s[tid] = 0.f; load_s[tid] = 0.f; }
    __syncthreads();

    const int e0 = lane, e1 = lane + 32;
    const float brv0 = br[e0], brv1 = br[e1];
    const float bnv0 = bn[e0], bnv1 = bn[e1];
    const int rowA = (blockIdx.x * 8 + wid) * 2;     // grid 1024: rows rowA, rowA+1
    const int rowB = rowA + 1;

    // ---- load + softplus + noisy logits for both rows (independent chains) ----
    const float* LA = g_lg + (size_t)rowA * 128;
    const float* LB = g_lg + (size_t)rowB * 128;
    float Araw0 = LA[e0] + brv0,      Araw1 = LA[e1] + brv1;
    float Braw0 = LB[e0] + brv0,      Braw1 = LB[e1] + brv1;
    float Apre0 = LA[64 + e0] + bnv0, Apre1 = LA[64 + e1] + bnv1;
    float Bpre0 = LB[64 + e0] + bnv0, Bpre1 = LB[64 + e1] + bnv1;
    float Asd0 = fmaxf(Apre0, 0.f) + log1pf(expf(-fabsf(Apre0))) + EPS_C;
    float Asd1 = fmaxf(Apre1, 0.f) + log1pf(expf(-fabsf(Apre1))) + EPS_C;
    float Bsd0 = fmaxf(Bpre0, 0.f) + log1pf(expf(-fabsf(Bpre0))) + EPS_C;
    float Bsd1 = fmaxf(Bpre1, 0.f) + log1pf(expf(-fabsf(Bpre1))) + EPS_C;
    float Anz0 = fmaf(neps[(size_t)rowA * NEXP + e0], Asd0, Araw0);
    float Anz1 = fmaf(neps[(size_t)rowA * NEXP + e1], Asd1, Araw1);
    float Bnz0 = fmaf(neps[(size_t)rowB * NEXP + e0], Bsd0, Braw0);
    float Bnz1 = fmaf(neps[(size_t)rowB * NEXP + e1], Bsd1, Braw1);
    float Ag0 = gum[(size_t)rowA * NEXP + e0], Ag1 = gum[(size_t)rowA * NEXP + e1];
    float Bg0 = gum[(size_t)rowB * NEXP + e0], Bg1 = gum[(size_t)rowB * NEXP + e1];

    // ---- top-9 for both rows, interleaved (exact, tie -> lowest idx) ----
    uint32_t Ak0 = ordkey(Anz0), Ak1 = ordkey(Anz1);
    uint32_t Bk0 = ordkey(Bnz0), Bk1 = ordkey(Bnz1);
    float Ah0 = 0.f, Ah1 = 0.f, Athr = 0.f, Am1 = 0.f;
    float Bh0 = 0.f, Bh1 = 0.f, Bthr = 0.f, Bm1 = 0.f;
    #pragma unroll 1
    for (int t = 0; t < KSEL; t++) {
        uint32_t MA = redux_max(Ak0 > Ak1 ? Ak0 : Ak1);
        uint32_t MB = redux_max(Bk0 > Bk1 ? Bk0 : Bk1);
        if (t == 0) { Am1 = ordinv(MA); Bm1 = ordinv(MB); }
        Athr = ordinv(MA); Bthr = ordinv(MB);
        unsigned Ab0 = __ballot_sync(0xffffffffu, Ak0 == MA);
        unsigned Bb0 = __ballot_sync(0xffffffffu, Bk0 == MB);
        if (Ab0) {
            if (lane == __ffs(Ab0) - 1) { Ah0 = 1.f; Ak0 = 0u; }
        } else {
            unsigned Ab1 = __ballot_sync(0xffffffffu, Ak1 == MA);
            if (lane == __ffs(Ab1) - 1) { Ah1 = 1.f; Ak1 = 0u; }
        }
        if (Bb0) {
            if (lane == __ffs(Bb0) - 1) { Bh0 = 1.f; Bk0 = 0u; }
        } else {
            unsigned Bb1 = __ballot_sync(0xffffffffu, Bk1 == MB);
            if (lane == __ffs(Bb1) - 1) { Bh1 = 1.f; Bk1 = 0u; }
        }
    }

    // ---- softmax maxes via redux (interleaved); fast exp/rcp ----
    float Am2 = ordinv(redux_max(ordkey(fmaxf(Anz0 + Ag0, Anz1 + Ag1))));
    float Bm2 = ordinv(redux_max(ordkey(fmaxf(Bnz0 + Bg0, Bnz1 + Bg1))));
    float Am3 = ordinv(redux_max(ordkey(fmaxf(Araw0, Araw1))));
    float Bm3 = ordinv(redux_max(ordkey(fmaxf(Braw0, Braw1))));

    float AE10 = __expf(Anz0 - Am1),       AE11 = __expf(Anz1 - Am1);
    float BE10 = __expf(Bnz0 - Bm1),       BE11 = __expf(Bnz1 - Bm1);
    float AE20 = __expf(Anz0 + Ag0 - Am2), AE21 = __expf(Anz1 + Ag1 - Am2);
    float BE20 = __expf(Bnz0 + Bg0 - Bm2), BE21 = __expf(Bnz1 + Bg1 - Bm2);
    float AE30 = __expf(Araw0 - Am3),      AE31 = __expf(Araw1 - Am3);
    float BE30 = __expf(Braw0 - Bm3),      BE31 = __expf(Braw1 - Bm3);

    float As1 = AE10 + AE11, Bs1 = BE10 + BE11;
    float As2 = AE20 + AE21, Bs2 = BE20 + BE21;
    float As3 = AE30 + AE31, Bs3 = BE30 + BE31;
    wsum2(As1, Bs1);
    wsum2(As2, Bs2);
    wsum2(As3, Bs3);
    float Ai1 = __fdividef(1.f, As1), Bi1 = __fdividef(1.f, Bs1);
    float Ai2 = __fdividef(1.f, As2), Bi2 = __fdividef(1.f, Bs2);
    float Ai3 = __fdividef(1.f, As3), Bi3 = __fdividef(1.f, Bs3);

    float Ams0 = AE20 * Ai2, Ams1 = AE21 * Ai2;
    float Bms0 = BE20 * Bi2, Bms1 = BE21 * Bi2;
    float* omA  = out + (size_t)rowA * NEXP;
    float* omB  = out + (size_t)rowB * NEXP;
    float* orpA = out + (size_t)N_TOK * NEXP + (size_t)rowA * NEXP;
    float* orpB = out + (size_t)N_TOK * NEXP + (size_t)rowB * NEXP;
    omA[e0]  = (Ah0 - Ams0) + Ams0;
    omA[e1]  = (Ah1 - Ams1) + Ams1;
    omB[e0]  = (Bh0 - Bms0) + Bms0;
    omB[e1]  = (Bh1 - Bms1) + Bms1;
    orpA[e0] = AE10 * Ai1;
    orpA[e1] = AE11 * Ai1;
    orpB[e0] = BE10 * Bi1;
    orpB[e1] = BE11 * Bi1;

    // erf kept exact: 45x slope on the load output
    float Az0 = (Athr - Araw0) / Asd0, Az1 = (Athr - Araw1) / Asd1;
    float Bz0 = (Bthr - Braw0) / Bsd0, Bz1 = (Bthr - Braw1) / Bsd1;
    float ld0 = 0.5f * (1.f - erff(Az0 * INV_SIG_SQRT2))
              + 0.5f * (1.f - erff(Bz0 * INV_SIG_SQRT2));
    float ld1 = 0.5f * (1.f - erff(Az1 * INV_SIG_SQRT2))
              + 0.5f * (1.f - erff(Bz1 * INV_SIG_SQRT2));
    float imp0 = AE30 * Ai3 + BE30 * Bi3;
    float imp1 = AE31 * Ai3 + BE31 * Bi3;

    atomicAdd(&imp_s[e0], imp0);
    atomicAdd(&imp_s[e1], imp1);
    atomicAdd(&load_s[e0], ld0);
    atomicAdd(&load_s[e1], ld1);
    __syncthreads();
    if (tid < 64) {
        atomicAdd(out + 2 * (size_t)N_TOK * NEXP + tid,        imp_s[tid]);
        atomicAdd(out + 2 * (size_t)N_TOK * NEXP + NEXP + tid, load_s[tid]);
    }
}

extern "C" void kernel_launch(void* const* d_in, const int* in_sizes, int n_in,
                              void* d_out, int out_size)
{
    const float* x    = (const float*)d_in[0];
    const float* Wr   = (const float*)d_in[1];
    const float* br   = (const float*)d_in[2];
    const float* Wn   = (const float*)d_in[3];
    const float* bn   = (const float*)d_in[4];
    const float* neps = (const float*)d_in[5];
    const float* gum  = (const float*)d_in[6];
    float* out = (float*)d_out;

    cudaFuncSetAttribute(gemm_kernel,
                         cudaFuncAttributeMaxDynamicSharedMemorySize, SMEM_BYTES);
    gemm_kernel<<<GRID, 256, SMEM_BYTES>>>(x, Wr, Wn, out);

    epi_kernel<<<N_TOK / 16, 256>>>(br, bn, neps, gum, out);
}